// round 16
// baseline (speedup 1.0000x reference)
#include <cuda_runtime.h>
#include <cuda_bf16.h>
#include <cstdint>

typedef __nv_bfloat16 bf16;
typedef __nv_bfloat162 bf162;

// ======================= device scratch (no allocs) =========================
__device__ bf16 g_qkvh[50331648];     // qkv (16384,3072) hi
__device__ bf16 g_qkvl[50331648];     // lo
__device__ bf16 g_qph[67108864];      // qproj (4,16,4096,256) hi
__device__ bf16 g_qpl[67108864];
__device__ bf16 g_kph[67108864];      // kproj
__device__ bf16 g_kpl[67108864];
__device__ float g_kvpart[4194304];   // kv partials (4 ksplit,64 bh,64 d,256 f)
__device__ float g_kspart[524288];    // ksum partials (128 rowtile,16 h,256 f)
__device__ bf16 g_kvTh[1310720];      // kvT+ksum (64 bh, 80 rows, 256 f)
__device__ bf16 g_kvTl[1310720];
__device__ bf16 g_attn_hi[16777216];  // attn (16384,1024)
__device__ bf16 g_attn_lo[16777216];
__device__ bf16 g_xhi[16777216];      // x split (16384,1024)
__device__ bf16 g_xlo[16777216];
__device__ bf16 g_wqkvT_hi[3145728];  // w_qkv^T (3072,1024)
__device__ bf16 g_wqkvT_lo[3145728];
__device__ bf16 g_woutT_hi[1048576];  // w_out^T (1024,1024)
__device__ bf16 g_woutT_lo[1048576];
__device__ bf16 g_projT_hi[262144];   // projT (16,256,64)
__device__ bf16 g_projT_lo[262144];

// ======================= PTX helpers ========================================
__device__ __forceinline__ uint32_t smem_u32(const void* p) {
    uint32_t a;
    asm("{ .reg .u64 t; cvta.to.shared.u64 t, %1; cvt.u32.u64 %0, t; }"
        : "=r"(a) : "l"(p));
    return a;
}
__device__ __forceinline__ void cp16(uint32_t saddr, const void* g) {
    asm volatile("cp.async.cg.shared.global [%0], [%1], 16;"
                 :: "r"(saddr), "l"(g) : "memory");
}
#define CP_COMMIT() asm volatile("cp.async.commit_group;" ::: "memory")
#define CP_WAIT2()  asm volatile("cp.async.wait_group 2;" ::: "memory")
#define CP_WAIT1()  asm volatile("cp.async.wait_group 1;" ::: "memory")
#define CP_WAIT0()  asm volatile("cp.async.wait_group 0;" ::: "memory")

__device__ __forceinline__ void ldsm4(uint32_t& r0, uint32_t& r1,
                                      uint32_t& r2, uint32_t& r3, uint32_t a) {
    asm volatile("ldmatrix.sync.aligned.m8n8.x4.shared.b16 {%0,%1,%2,%3}, [%4];"
                 : "=r"(r0), "=r"(r1), "=r"(r2), "=r"(r3) : "r"(a));
}
__device__ __forceinline__ void ldsm4t(uint32_t& r0, uint32_t& r1,
                                       uint32_t& r2, uint32_t& r3, uint32_t a) {
    asm volatile("ldmatrix.sync.aligned.m8n8.x4.trans.shared.b16 {%0,%1,%2,%3}, [%4];"
                 : "=r"(r0), "=r"(r1), "=r"(r2), "=r"(r3) : "r"(a));
}
__device__ __forceinline__ void ldsm2(uint32_t& r0, uint32_t& r1, uint32_t a) {
    asm volatile("ldmatrix.sync.aligned.m8n8.x2.shared.b16 {%0,%1}, [%2];"
                 : "=r"(r0), "=r"(r1) : "r"(a));
}
__device__ __forceinline__ void mma16816(float* c, const uint32_t* a,
                                         const uint32_t* b) {
    asm volatile(
        "mma.sync.aligned.m16n8k16.row.col.f32.bf16.bf16.f32 "
        "{%0,%1,%2,%3}, {%4,%5,%6,%7}, {%8,%9}, {%0,%1,%2,%3};"
        : "+f"(c[0]), "+f"(c[1]), "+f"(c[2]), "+f"(c[3])
        : "r"(a[0]), "r"(a[1]), "r"(a[2]), "r"(a[3]), "r"(b[0]), "r"(b[1]));
}
__device__ __forceinline__ void split2(float v, bf16& h, bf16& l) {
    h = __float2bfloat16(v);
    l = __float2bfloat16(v - __bfloat162float(h));
}

// ======================= big HMMA GEMM (qkv / out), persistent ==============
static constexpr int PITCH_G  = 80;
static constexpr int T_128    = 128 * PITCH_G;      // 10240
static constexpr int STAGE_G  = 4 * T_128;          // 40960 (Ah, Al, Bh, Bl)
static constexpr int GEMM_SMEM = 2 * STAGE_G;       // 81920

template<bool BIAS, bool SPLITOUT>
__global__ __launch_bounds__(128, 2) void hmma_gemm(
    const bf16* __restrict__ Ahi, const bf16* __restrict__ Alo,
    const bf16* __restrict__ Bhi, const bf16* __restrict__ Blo,
    const float* __restrict__ bias, float* __restrict__ C,
    bf16* __restrict__ Chi, bf16* __restrict__ Clo, int N, int K, int ntX, int ntY)
{
    extern __shared__ char smem[];
    const uint32_t sbase = smem_u32(smem);
    const int tid = threadIdx.x;
    const int wid = tid >> 5, lane = tid & 31;
    const int warpM = wid & 1, warpN = wid >> 1;
    const int NC = K >> 5;
    const int ntiles = ntX * ntY;

    for (int tile = blockIdx.x; tile < ntiles; tile += gridDim.x) {
        const int m0 = (tile / ntX) * 128;
        const int n0 = (tile % ntX) * 128;

        float acc[4][8][4];
        #pragma unroll
        for (int i = 0; i < 4; i++)
            #pragma unroll
            for (int j = 0; j < 8; j++)
                #pragma unroll
                for (int q = 0; q < 4; q++) acc[i][j][q] = 0.f;

        auto load_stage = [&](int c, int s) {
            const uint32_t sb = sbase + s * STAGE_G;
            #pragma unroll
            for (int i = 0; i < 16; i++) {
                int idx = tid + i * 128;
                int rc = idx >> 2, ch = idx & 3;
                int t = rc >> 7;
                int row = rc & 127;
                const bf16* g;
                if (t == 0)      g = Ahi + (size_t)(m0 + row) * K;
                else if (t == 1) g = Alo + (size_t)(m0 + row) * K;
                else if (t == 2) g = Bhi + (size_t)(n0 + row) * K;
                else             g = Blo + (size_t)(n0 + row) * K;
                cp16(sb + t * T_128 + row * PITCH_G + ch * 16, g + c * 32 + ch * 8);
            }
            CP_COMMIT();
        };

        load_stage(0, 0);

        for (int c = 0; c < NC; c++) {
            const int s = c & 1;
            if (c + 1 < NC) { load_stage(c + 1, s ^ 1); CP_WAIT1(); }
            else            { CP_WAIT0(); }
            __syncthreads();

            const uint32_t sb = sbase + s * STAGE_G;
            const uint32_t Ah = sb, Al = sb + T_128;
            const uint32_t Bh = sb + 2 * T_128, Bl = sb + 3 * T_128;

            #pragma unroll
            for (int ks = 0; ks < 2; ks++) {
                uint32_t ahi[4][4], alo[4][4];
                #pragma unroll
                for (int mt = 0; mt < 4; mt++) {
                    int r = warpM * 64 + mt * 16 + (lane & 15);
                    uint32_t off = r * PITCH_G + (ks * 2 + (lane >> 4)) * 16;
                    ldsm4(ahi[mt][0], ahi[mt][1], ahi[mt][2], ahi[mt][3], Ah + off);
                    ldsm4(alo[mt][0], alo[mt][1], alo[mt][2], alo[mt][3], Al + off);
                }
                #pragma unroll
                for (int tp = 0; tp < 4; tp++) {
                    uint32_t bh2[2][2], bl2[2][2];
                    int nr = warpN * 64 + tp * 16 + ((lane >> 4) << 3) + (lane & 7);
                    uint32_t off = nr * PITCH_G + (ks * 2 + ((lane >> 3) & 1)) * 16;
                    ldsm4(bh2[0][0], bh2[0][1], bh2[1][0], bh2[1][1], Bh + off);
                    ldsm4(bl2[0][0], bl2[0][1], bl2[1][0], bl2[1][1], Bl + off);
                    #pragma unroll
                    for (int mt = 0; mt < 4; mt++)
                        #pragma unroll
                        for (int p = 0; p < 2; p++) {
                            mma16816(acc[mt][2 * tp + p], ahi[mt], bh2[p]);
                            mma16816(acc[mt][2 * tp + p], ahi[mt], bl2[p]);
                            mma16816(acc[mt][2 * tp + p], alo[mt], bh2[p]);
                        }
                }
            }
            __syncthreads();
        }

        #pragma unroll
        for (int mt = 0; mt < 4; mt++) {
            int r0 = m0 + warpM * 64 + mt * 16 + (lane >> 2);
            #pragma unroll
            for (int nt = 0; nt < 8; nt++) {
                int col = n0 + warpN * 64 + nt * 8 + (lane & 3) * 2;
                if (SPLITOUT) {
                    bf16 h0, l0, h1, l1;
                    split2(acc[mt][nt][0], h0, l0);
                    split2(acc[mt][nt][1], h1, l1);
                    *(bf162*)(Chi + (size_t)r0 * N + col) = bf162(h0, h1);
                    *(bf162*)(Clo + (size_t)r0 * N + col) = bf162(l0, l1);
                    split2(acc[mt][nt][2], h0, l0);
                    split2(acc[mt][nt][3], h1, l1);
                    *(bf162*)(Chi + (size_t)(r0 + 8) * N + col) = bf162(h0, h1);
                    *(bf162*)(Clo + (size_t)(r0 + 8) * N + col) = bf162(l0, l1);
                } else {
                    float2 v0 = {acc[mt][nt][0], acc[mt][nt][1]};
                    float2 v1 = {acc[mt][nt][2], acc[mt][nt][3]};
                    if (BIAS) {
                        float2 bv = *(const float2*)(bias + col);
                        v0.x += bv.x; v0.y += bv.y;
                        v1.x += bv.x; v1.y += bv.y;
                    }
                    *(float2*)(C + (size_t)r0 * N + col)       = v0;
                    *(float2*)(C + (size_t)(r0 + 8) * N + col) = v1;
                }
            }
        }
        __syncthreads();
    }
}

// ======================= proj: elu1(slice @ projT) via HMMA =================
static constexpr int PITCH_B = 144;
static constexpr int PROJ_SMEM = 4 * 18432;

__global__ __launch_bounds__(256, 2) void proj_mma()
{
    extern __shared__ char smem[];
    const uint32_t sbase = smem_u32(smem);
    const int tid = threadIdx.x;
    const int wid = tid >> 5, lane = tid & 31;
    const int warpM = wid & 3, warpN = wid >> 2;
    const int z = blockIdx.z;
    const int sel = z & 1, h = z >> 1;
    const int m0 = blockIdx.y * 128;
    const int fbase = blockIdx.x * 128;
    const int aoff = sel * 1024 + h * 64;

    #pragma unroll
    for (int i = 0; i < 16; i++) {
        int idx = tid + i * 256;
        int half = idx >> 11;
        int idx2 = idx & 2047;
        int hl = idx2 >> 10;
        int rem = idx2 & 1023;
        int row = rem >> 3, ch = rem & 7;
        if (half == 0) {
            const bf16* g = (hl ? g_qkvl : g_qkvh) + (size_t)(m0 + row) * 3072 + aoff + ch * 8;
            cp16(sbase + hl * 18432 + row * PITCH_B + ch * 16, g);
        } else {
            const bf16* g = (hl ? g_projT_lo : g_projT_hi) + ((size_t)h * 256 + fbase + row) * 64 + ch * 8;
            cp16(sbase + 36864 + hl * 18432 + row * PITCH_B + ch * 16, g);
        }
    }
    CP_COMMIT();
    CP_WAIT0();
    __syncthreads();

    float acc[2][8][4];
    #pragma unroll
    for (int i = 0; i < 2; i++)
        #pragma unroll
        for (int j = 0; j < 8; j++)
            #pragma unroll
            for (int q = 0; q < 4; q++) acc[i][j][q] = 0.f;

    const uint32_t Ah = sbase, Al = sbase + 18432;
    const uint32_t Bh = sbase + 36864, Bl = sbase + 55296;

    #pragma unroll
    for (int ks = 0; ks < 4; ks++) {
        uint32_t ahi[2][4], alo[2][4];
        #pragma unroll
        for (int mt = 0; mt < 2; mt++) {
            int r = warpM * 32 + mt * 16 + (lane & 15);
            uint32_t off = r * PITCH_B + (ks * 2 + (lane >> 4)) * 16;
            ldsm4(ahi[mt][0], ahi[mt][1], ahi[mt][2], ahi[mt][3], Ah + off);
            ldsm4(alo[mt][0], alo[mt][1], alo[mt][2], alo[mt][3], Al + off);
        }
        #pragma unroll
        for (int tp = 0; tp < 4; tp++) {
            uint32_t bh[2][2], bl[2][2];
            int nr = warpN * 64 + tp * 16 + ((lane >> 4) << 3) + (lane & 7);
            uint32_t off = nr * PITCH_B + (ks * 2 + ((lane >> 3) & 1)) * 16;
            ldsm4(bh[0][0], bh[0][1], bh[1][0], bh[1][1], Bh + off);
            ldsm4(bl[0][0], bl[0][1], bl[1][0], bl[1][1], Bl + off);
            #pragma unroll
            for (int mt = 0; mt < 2; mt++)
                #pragma unroll
                for (int p = 0; p < 2; p++) {
                    mma16816(acc[mt][2 * tp + p], ahi[mt], bh[p]);
                    mma16816(acc[mt][2 * tp + p], ahi[mt], bl[p]);
                    mma16816(acc[mt][2 * tp + p], alo[mt], bh[p]);
                }
        }
    }

    bf16* oh = sel ? g_kph : g_qph;
    bf16* ol = sel ? g_kpl : g_qpl;
    const int b = m0 >> 12;
    const size_t bhbase = ((size_t)(b * 16 + h)) * 4096 * 256;

    float cs[16];
    #pragma unroll
    for (int i = 0; i < 16; i++) cs[i] = 0.f;

    #pragma unroll
    for (int mt = 0; mt < 2; mt++) {
        int rl0 = warpM * 32 + mt * 16 + (lane >> 2);
        #pragma unroll
        for (int nt = 0; nt < 8; nt++) {
            int col = warpN * 64 + nt * 8 + (lane & 3) * 2;
            float e[4];
            #pragma unroll
            for (int q = 0; q < 4; q++) {
                float v = acc[mt][nt][q];
                e[q] = v > 0.f ? v + 1.f : __expf(v);
                cs[nt * 2 + (q & 1)] += e[q];
            }
            int n0r = m0 + rl0 - b * 4096;
            size_t o0 = bhbase + (size_t)n0r * 256 + fbase + col;
            size_t o1 = o0 + 8 * 256;
            bf16 h0, l0, h1, l1;
            split2(e[0], h0, l0); split2(e[1], h1, l1);
            *(bf162*)(oh + o0) = bf162(h0, h1);
            *(bf162*)(ol + o0) = bf162(l0, l1);
            split2(e[2], h0, l0); split2(e[3], h1, l1);
            *(bf162*)(oh + o1) = bf162(h0, h1);
            *(bf162*)(ol + o1) = bf162(l0, l1);
        }
    }

    if (sel == 1) {
        __syncthreads();
        float* sums = (float*)smem;
        int slot = warpM * 8 + (lane >> 2);
        #pragma unroll
        for (int nt = 0; nt < 8; nt++)
            #pragma unroll
            for (int cp = 0; cp < 2; cp++) {
                int col = warpN * 64 + nt * 8 + (lane & 3) * 2 + cp;
                sums[col * 32 + slot] = cs[nt * 2 + cp];
            }
        __syncthreads();
        if (tid < 128) {
            float s = 0.f;
            #pragma unroll
            for (int i = 0; i < 32; i++) s += sums[tid * 32 + i];
            g_kspart[((size_t)blockIdx.y * 16 + h) * 256 + fbase + tid] = s;
        }
    }
}

// ======================= kv: v^T @ kproj via trans-HMMA, f-split + 3-stage ==
// grid (8 = kc*? , 64 bh): x = fh*4 + kc. M=64 (d), N=128 (f half), K=1024.
// 8 warps 2M x 4N, warp tile 32x32. Stage 26624B, 3 stages, 2 CTAs/SM.
static constexpr int KV_A_T = 32 * 144;     // 4608
static constexpr int KV_B_T = 32 * 272;     // 8704 (128 f cols + 16B pad)
static constexpr int KV_STAGE = 2 * KV_A_T + 2 * KV_B_T;  // 26624
static constexpr int KV_SMEM = 3 * KV_STAGE;              // 79872

__global__ __launch_bounds__(256, 2) void kv_mma()
{
    extern __shared__ char smem[];
    const uint32_t sbase = smem_u32(smem);
    const int tid = threadIdx.x;
    const int wid = tid >> 5, lane = tid & 31;
    const int warpM = wid >> 2, warpN = wid & 3;     // 2M x 4N
    const int kc = blockIdx.x & 3;
    const int fh = blockIdx.x >> 2;                  // 0..1
    const int bh = blockIdx.y;
    const int b = bh >> 4, h = bh & 15;
    const int f0 = fh * 128;

    float acc[2][4][4];
    #pragma unroll
    for (int i = 0; i < 2; i++)
        #pragma unroll
        for (int j = 0; j < 4; j++)
            #pragma unroll
            for (int q = 0; q < 4; q++) acc[i][j][q] = 0.f;

    auto load_stage = [&](int c, int s) {
        const uint32_t sb = sbase + s * KV_STAGE;
        const int n0 = kc * 1024 + c * 32;
        #pragma unroll
        for (int i = 0; i < 6; i++) {
            int idx = tid + i * 256;
            if (idx < 512) {
                int hl = idx >> 8, rem = idx & 255;
                int row = rem >> 3, ch = rem & 7;
                const bf16* g = (hl ? g_qkvl : g_qkvh) +
                    (size_t)(b * 4096 + n0 + row) * 3072 + 2048 + h * 64 + ch * 8;
                cp16(sb + hl * KV_A_T + row * 144 + ch * 16, g);
            } else {
                int idx2 = idx - 512;                // 0..1023
                int hl = idx2 >> 9, rem = idx2 & 511;
                int row = rem >> 4, ch = rem & 15;
                const bf16* g = (hl ? g_kpl : g_kph) +
                    ((size_t)bh * 4096 + n0 + row) * 256 + f0 + ch * 8;
                cp16(sb + 2 * KV_A_T + hl * KV_B_T + row * 272 + ch * 16, g);
            }
        }
        CP_COMMIT();
    };

    load_stage(0, 0);
    load_stage(1, 1);
    for (int c = 0; c < 32; c++) {
        const int s = c - (c / 3) * 3;               // c % 3
        if (c + 2 < 32) {
            int s2 = (c + 2) - ((c + 2) / 3) * 3;
            load_stage(c + 2, s2);
            CP_WAIT2();
        } else if (c + 1 < 32) {
            CP_WAIT1();
        } else {
            CP_WAIT0();
        }
        __syncthreads();

        const uint32_t sb = sbase + s * KV_STAGE;
        const uint32_t Ah = sb, Al = sb + KV_A_T;
        const uint32_t Bh = sb + 2 * KV_A_T, Bl = sb + 2 * KV_A_T + KV_B_T;

        #pragma unroll
        for (int ks = 0; ks < 2; ks++) {
            const int kbase = ks * 16;
            uint32_t ahi[2][4], alo[2][4];
            #pragma unroll
            for (int mt = 0; mt < 2; mt++) {
                int md = warpM * 32 + mt * 16 + ((lane >> 3) & 1) * 8;
                int krow = kbase + (lane >> 4) * 8 + (lane & 7);
                uint32_t off = krow * 144 + md * 2;
                ldsm4t(ahi[mt][0], ahi[mt][1], ahi[mt][2], ahi[mt][3], Ah + off);
                ldsm4t(alo[mt][0], alo[mt][1], alo[mt][2], alo[mt][3], Al + off);
            }
            #pragma unroll
            for (int tp = 0; tp < 2; tp++) {
                uint32_t bh2[2][2], bl2[2][2];
                int krow = kbase + ((lane >> 3) & 1) * 8 + (lane & 7);
                int ncol = warpN * 32 + tp * 16 + (lane >> 4) * 8;
                uint32_t off = krow * 272 + ncol * 2;
                ldsm4t(bh2[0][0], bh2[0][1], bh2[1][0], bh2[1][1], Bh + off);
                ldsm4t(bl2[0][0], bl2[0][1], bl2[1][0], bl2[1][1], Bl + off);
                #pragma unroll
                for (int mt = 0; mt < 2; mt++)
                    #pragma unroll
                    for (int p = 0; p < 2; p++) {
                        mma16816(acc[mt][2 * tp + p], ahi[mt], bh2[p]);
                        mma16816(acc[mt][2 * tp + p], ahi[mt], bl2[p]);
                        mma16816(acc[mt][2 * tp + p], alo[mt], bh2[p]);
                    }
            }
        }
        __syncthreads();
    }

    float* out = g_kvpart + ((size_t)kc * 64 + bh) * 16384;
    #pragma unroll
    for (int mt = 0; mt < 2; mt++) {
        int d0 = warpM * 32 + mt * 16 + (lane >> 2);
        #pragma unroll
        for (int nt = 0; nt < 4; nt++) {
            int col = f0 + warpN * 32 + nt * 8 + (lane & 3) * 2;
            *(float2*)(out + (size_t)d0 * 256 + col) =
                make_float2(acc[mt][nt][0], acc[mt][nt][1]);
            *(float2*)(out + (size_t)(d0 + 8) * 256 + col) =
                make_float2(acc[mt][nt][2], acc[mt][nt][3]);
        }
    }
}

// ======================= kv combine =========================================
__global__ void kv_combine()
{
    const int row = blockIdx.x;
    const int bh = blockIdx.y;
    const int f = threadIdx.x;
    float s = 0.f;
    if (row < 64) {
        #pragma unroll
        for (int kc = 0; kc < 4; kc++)
            s += g_kvpart[((size_t)kc * 64 + bh) * 16384 + row * 256 + f];
    } else if (row == 64) {
        const int b = bh >> 4, h = bh & 15;
        for (int i = 0; i < 32; i++)
            s += g_kspart[((size_t)(b * 32 + i) * 16 + h) * 256 + f];
    }
    bf16 hh, ll;
    split2(s, hh, ll);
    g_kvTh[((size_t)bh * 80 + row) * 256 + f] = hh;
    g_kvTl[((size_t)bh * 80 + row) * 256 + f] = ll;
}

// ======================= attn: qproj @ [kv|ksum] + z-norm, 3-stage ==========
static constexpr int AT_A_T = 128 * 80;
static constexpr int AT_B_T = 80 * 80;
static constexpr int AT_STAGE = 2 * AT_A_T + 2 * AT_B_T;  // 33280
static constexpr int AT_SMEM = 3 * AT_STAGE;              // 99840

__global__ __launch_bounds__(256, 2) void attn_mma()
{
    extern __shared__ char smem[];
    __shared__ float zs[128];
    const uint32_t sbase = smem_u32(smem);
    const int tid = threadIdx.x;
    const int wid = tid >> 5, lane = tid & 31;
    const int warpM = wid & 3, warpN = wid >> 2;
    const int nbase = blockIdx.x * 128;
    const int bh = blockIdx.y;
    const int b = bh >> 4, h = bh & 15;

    float acc[2][5][4];
    #pragma unroll
    for (int i = 0; i < 2; i++)
        #pragma unroll
        for (int j = 0; j < 5; j++)
            #pragma unroll
            for (int q = 0; q < 4; q++) acc[i][j][q] = 0.f;

    auto load_stage = [&](int c, int s) {
        const uint32_t sb = sbase + s * AT_STAGE;
        const int k0 = c * 32;
        #pragma unroll
        for (int i = 0; i < 7; i++) {
            int idx = tid + i * 256;
            if (idx >= 1664) break;
            if (idx < 1024) {
                int hl = idx >> 9, rem = idx & 511;
                int row = rem >> 2, ch = rem & 3;
                const bf16* g = (hl ? g_qpl : g_qph) +
                    ((size_t)bh * 4096 + nbase + row) * 256 + k0 + ch * 8;
                cp16(sb + hl * AT_A_T + row * 80 + ch * 16, g);
            } else {
                int idx2 = idx - 1024;
                int hl = idx2 >= 320 ? 1 : 0;
                int rem = idx2 - hl * 320;
                int row = rem >> 2, ch = rem & 3;
                const bf16* g = (hl ? g_kvTl : g_kvTh) +
                    ((size_t)bh * 80 + row) * 256 + k0 + ch * 8;
                cp16(sb + 2 * AT_A_T + hl * AT_B_T + row * 80 + ch * 16, g);
            }
        }
        CP_COMMIT();
    };

    load_stage(0, 0);
    load_stage(1, 1);
    for (int c = 0; c < 8; c++) {
        const int s = c - (c / 3) * 3;
        if (c + 2 < 8) {
            int s2 = (c + 2) - ((c + 2) / 3) * 3;
            load_stage(c + 2, s2);
            CP_WAIT2();
        } else if (c + 1 < 8) {
            CP_WAIT1();
        } else {
            CP_WAIT0();
        }
        __syncthreads();

        const uint32_t sb = sbase + s * AT_STAGE;
        const uint32_t Ah = sb, Al = sb + AT_A_T;
        const uint32_t Bh = sb + 2 * AT_A_T, Bl = sb + 2 * AT_A_T + AT_B_T;

        #pragma unroll
        for (int ks = 0; ks < 2; ks++) {
            uint32_t ahi[2][4], alo[2][4];
            #pragma unroll
            for (int mt = 0; mt < 2; mt++) {
                int r = warpM * 32 + mt * 16 + (lane & 15);
                uint32_t off = r * 80 + (ks * 2 + (lane >> 4)) * 16;
                ldsm4(ahi[mt][0], ahi[mt][1], ahi[mt][2], ahi[mt][3], Ah + off);
                ldsm4(alo[mt][0], alo[mt][1], alo[mt][2], alo[mt][3], Al + off);
            }
            #pragma unroll
            for (int tp = 0; tp < 2; tp++) {
                uint32_t bh2[2][2], bl2[2][2];
                int nr = warpN * 40 + tp * 16 + ((lane >> 4) << 3) + (lane & 7);
                uint32_t off = nr * 80 + (ks * 2 + ((lane >> 3) & 1)) * 16;
                ldsm4(bh2[0][0], bh2[0][1], bh2[1][0], bh2[1][1], Bh + off);
                ldsm4(bl2[0][0], bl2[0][1], bl2[1][0], bl2[1][1], Bl + off);
                #pragma unroll
                for (int mt = 0; mt < 2; mt++)
                    #pragma unroll
                    for (int p = 0; p < 2; p++) {
                        mma16816(acc[mt][2 * tp + p], ahi[mt], bh2[p]);
                        mma16816(acc[mt][2 * tp + p], ahi[mt], bl2[p]);
                        mma16816(acc[mt][2 * tp + p], alo[mt], bh2[p]);
                    }
            }
            {
                uint32_t bh2[2], bl2[2];
                int nr = warpN * 40 + 32 + (lane & 7);
                uint32_t off = nr * 80 + (ks * 2 + ((lane >> 3) & 1)) * 16;
                ldsm2(bh2[0], bh2[1], Bh + off);
                ldsm2(bl2[0], bl2[1], Bl + off);
                #pragma unroll
                for (int mt = 0; mt < 2; mt++) {
                    mma16816(acc[mt][4], ahi[mt], bh2);
                    mma16816(acc[mt][4], ahi[mt], bl2);
                    mma16816(acc[mt][4], alo[mt], bh2);
                }
            }
        }
        __syncthreads();
    }

    if (warpN == 1 && (lane & 3) == 0) {
        #pragma unroll
        for (int mt = 0; mt < 2; mt++) {
            int r0 = warpM * 32 + mt * 16 + (lane >> 2);
            zs[r0] = acc[mt][3][0];
            zs[r0 + 8] = acc[mt][3][2];
        }
    }
    __syncthreads();

    #pragma unroll
    for (int mt = 0; mt < 2; mt++) {
        int rl0 = warpM * 32 + mt * 16 + (lane >> 2);
        float zi0 = 1.0f / (zs[rl0] + 1e-8f);
        float zi1 = 1.0f / (zs[rl0 + 8] + 1e-8f);
        #pragma unroll
        for (int nt = 0; nt < 5; nt++) {
            int col = warpN * 40 + nt * 8 + (lane & 3) * 2;
            if (col >= 64) continue;
            size_t o0 = ((size_t)(b * 4096 + nbase + rl0)) * 1024 + h * 64 + col;
            size_t o1 = o0 + 8 * 1024;
            bf16 h0, l0, h1, l1;
            split2(acc[mt][nt][0] * zi0, h0, l0);
            split2(acc[mt][nt][1] * zi0, h1, l1);
            *(bf162*)(g_attn_hi + o0) = bf162(h0, h1);
            *(bf162*)(g_attn_lo + o0) = bf162(l0, l1);
            split2(acc[mt][nt][2] * zi1, h0, l0);
            split2(acc[mt][nt][3] * zi1, h1, l1);
            *(bf162*)(g_attn_hi + o1) = bf162(h0, h1);
            *(bf162*)(g_attn_lo + o1) = bf162(l0, l1);
        }
    }
}

// ======================= conversion kernels =================================
__global__ void split_f32(const float* __restrict__ in,
                          bf16* __restrict__ hi, bf16* __restrict__ lo, int n4)
{
    int i = blockIdx.x * blockDim.x + threadIdx.x;
    if (i >= n4) return;
    float4 v = ((const float4*)in)[i];
    bf16 h0, l0, h1, l1, h2, l2, h3, l3;
    split2(v.x, h0, l0); split2(v.y, h1, l1);
    split2(v.z, h2, l2); split2(v.w, h3, l3);
    ((bf162*)hi)[2 * i]     = bf162(h0, h1);
    ((bf162*)hi)[2 * i + 1] = bf162(h2, h3);
    ((bf162*)lo)[2 * i]     = bf162(l0, l1);
    ((bf162*)lo)[2 * i + 1] = bf162(l2, l3);
}

__global__ void split_wT(const float* __restrict__ w,
                         bf16* __restrict__ thi, bf16* __restrict__ tlo,
                         int K, int N)
{
    __shared__ float t[32][33];
    int bx = blockIdx.x * 32, by = blockIdx.y * 32;
    int tx = threadIdx.x, ty = threadIdx.y;
    #pragma unroll
    for (int i = 0; i < 32; i += 8)
        t[ty + i][tx] = w[(size_t)(by + ty + i) * N + bx + tx];
    __syncthreads();
    #pragma unroll
    for (int i = 0; i < 32; i += 8) {
        bf16 hh, ll;
        split2(t[tx][ty + i], hh, ll);
        size_t o = (size_t)(bx + ty + i) * K + by + tx;
        thi[o] = hh;
        tlo[o] = ll;
    }
}

__global__ void split_projT(const float* __restrict__ proj)
{
    __shared__ float t[64][33];
    const int f0 = blockIdx.x * 32;
    const int h = blockIdx.y;
    const int tid = threadIdx.x;
    #pragma unroll
    for (int i = 0; i < 8; i++) {
        int e = tid + i * 256;
        int d = e >> 5, fi = e & 31;
        t[d][fi] = proj[(size_t)h * 16384 + d * 256 + f0 + fi];
    }
    __syncthreads();
    #pragma unroll
    for (int i = 0; i < 8; i++) {
        int e = tid + i * 256;
        int fi = e >> 6, d = e & 63;
        bf16 hh, ll;
        split2(t[d][fi], hh, ll);
        size_t o = ((size_t)h * 256 + f0 + fi) * 64 + d;
        g_projT_hi[o] = hh;
        g_projT_lo[o] = ll;
    }
}

// ===========================================================================
extern "C" void kernel_launch(void* const* d_in, const int* in_sizes, int n_in,
                              void* d_out, int out_size)
{
    const float* x      = (const float*)d_in[0];
    const float* w_qkv  = (const float*)d_in[1];
    const float* proj   = (const float*)d_in[2];
    const float* w_out  = (const float*)d_in[3];
    const float* b_out  = (const float*)d_in[4];
    float* out = (float*)d_out;

    cudaFuncSetAttribute(hmma_gemm<false, true>,
                         cudaFuncAttributeMaxDynamicSharedMemorySize, GEMM_SMEM);
    cudaFuncSetAttribute(hmma_gemm<true, false>,
                         cudaFuncAttributeMaxDynamicSharedMemorySize, GEMM_SMEM);
    cudaFuncSetAttribute(proj_mma,
                         cudaFuncAttributeMaxDynamicSharedMemorySize, PROJ_SMEM);
    cudaFuncSetAttribute(kv_mma,
                         cudaFuncAttributeMaxDynamicSharedMemorySize, KV_SMEM);
    cudaFuncSetAttribute(attn_mma,
                         cudaFuncAttributeMaxDynamicSharedMemorySize, AT_SMEM);

    bf16 *xhi, *xlo, *wqh, *wql, *woh, *wol, *qh, *ql, *ahi, *alo;
    cudaGetSymbolAddress((void**)&xhi, g_xhi);
    cudaGetSymbolAddress((void**)&xlo, g_xlo);
    cudaGetSymbolAddress((void**)&wqh, g_wqkvT_hi);
    cudaGetSymbolAddress((void**)&wql, g_wqkvT_lo);
    cudaGetSymbolAddress((void**)&woh, g_woutT_hi);
    cudaGetSymbolAddress((void**)&wol, g_woutT_lo);
    cudaGetSymbolAddress((void**)&qh, g_qkvh);
    cudaGetSymbolAddress((void**)&ql, g_qkvl);
    cudaGetSymbolAddress((void**)&ahi, g_attn_hi);
    cudaGetSymbolAddress((void**)&alo, g_attn_lo);

    split_f32<<<16384, 256>>>(x, xhi, xlo, 16777216 / 4);
    split_wT<<<dim3(96, 32), dim3(32, 8)>>>(w_qkv, wqh, wql, 1024, 3072);
    split_wT<<<dim3(32, 32), dim3(32, 8)>>>(w_out, woh, wol, 1024, 1024);
    split_projT<<<dim3(8, 16), 256>>>(proj);

    hmma_gemm<false, true><<<296, 128, GEMM_SMEM>>>(
        xhi, xlo, wqh, wql, nullptr, nullptr, qh, ql, 3072, 1024, 24, 128);

    proj_mma<<<dim3(2, 128, 32), 256, PROJ_SMEM>>>();

    // kv: f-split (2) x ksplit (4) = 8 x-tiles, 3-stage pipeline
    kv_mma<<<dim3(8, 64), 256, KV_SMEM>>>();
    kv_combine<<<dim3(80, 64), 256>>>();

    attn_mma<<<dim3(32, 64), 256, AT_SMEM>>>();

    hmma_gemm<true, false><<<296, 128, GEMM_SMEM>>>(
        ahi, alo, woh, wol, b_out, out, nullptr, nullptr, 1024, 1024, 8, 128);
}

// round 17
// speedup vs baseline: 1.0228x; 1.0228x over previous
#include <cuda_runtime.h>
#include <cuda_bf16.h>
#include <cstdint>

typedef __nv_bfloat16 bf16;
typedef __nv_bfloat162 bf162;

// ======================= device scratch (no allocs) =========================
__device__ bf16 g_qkvh[50331648];     // qkv (16384,3072) hi
__device__ bf16 g_qkvl[50331648];     // lo
__device__ bf16 g_qph[67108864];      // qproj (4,16,4096,256) hi
__device__ bf16 g_qpl[67108864];
__device__ bf16 g_kph[67108864];      // kproj
__device__ bf16 g_kpl[67108864];
__device__ float g_kvpart[4194304];   // kv partials (4 ksplit,64 bh,64 d,256 f)
__device__ float g_kspart[524288];    // ksum partials (128 rowtile,16 h,256 f)
__device__ bf16 g_kvTh[1310720];      // kvT+ksum (64 bh, 80 rows, 256 f)
__device__ bf16 g_kvTl[1310720];
__device__ bf16 g_attn_hi[16777216];  // attn (16384,1024)
__device__ bf16 g_attn_lo[16777216];
__device__ bf16 g_xhi[16777216];      // x split (16384,1024)
__device__ bf16 g_xlo[16777216];
__device__ bf16 g_wqkvT_hi[3145728];  // w_qkv^T (3072,1024)
__device__ bf16 g_wqkvT_lo[3145728];
__device__ bf16 g_woutT_hi[1048576];  // w_out^T (1024,1024)
__device__ bf16 g_woutT_lo[1048576];
__device__ bf16 g_projT_hi[262144];   // projT (16,256,64)
__device__ bf16 g_projT_lo[262144];

// ======================= PTX helpers ========================================
__device__ __forceinline__ uint32_t smem_u32(const void* p) {
    uint32_t a;
    asm("{ .reg .u64 t; cvta.to.shared.u64 t, %1; cvt.u32.u64 %0, t; }"
        : "=r"(a) : "l"(p));
    return a;
}
__device__ __forceinline__ void cp16(uint32_t saddr, const void* g) {
    asm volatile("cp.async.cg.shared.global [%0], [%1], 16;"
                 :: "r"(saddr), "l"(g) : "memory");
}
#define CP_COMMIT() asm volatile("cp.async.commit_group;" ::: "memory")
#define CP_WAIT2()  asm volatile("cp.async.wait_group 2;" ::: "memory")
#define CP_WAIT1()  asm volatile("cp.async.wait_group 1;" ::: "memory")
#define CP_WAIT0()  asm volatile("cp.async.wait_group 0;" ::: "memory")

__device__ __forceinline__ void ldsm4(uint32_t& r0, uint32_t& r1,
                                      uint32_t& r2, uint32_t& r3, uint32_t a) {
    asm volatile("ldmatrix.sync.aligned.m8n8.x4.shared.b16 {%0,%1,%2,%3}, [%4];"
                 : "=r"(r0), "=r"(r1), "=r"(r2), "=r"(r3) : "r"(a));
}
__device__ __forceinline__ void ldsm4t(uint32_t& r0, uint32_t& r1,
                                       uint32_t& r2, uint32_t& r3, uint32_t a) {
    asm volatile("ldmatrix.sync.aligned.m8n8.x4.trans.shared.b16 {%0,%1,%2,%3}, [%4];"
                 : "=r"(r0), "=r"(r1), "=r"(r2), "=r"(r3) : "r"(a));
}
__device__ __forceinline__ void ldsm2(uint32_t& r0, uint32_t& r1, uint32_t a) {
    asm volatile("ldmatrix.sync.aligned.m8n8.x2.shared.b16 {%0,%1}, [%2];"
                 : "=r"(r0), "=r"(r1) : "r"(a));
}
__device__ __forceinline__ void mma16816(float* c, const uint32_t* a,
                                         const uint32_t* b) {
    asm volatile(
        "mma.sync.aligned.m16n8k16.row.col.f32.bf16.bf16.f32 "
        "{%0,%1,%2,%3}, {%4,%5,%6,%7}, {%8,%9}, {%0,%1,%2,%3};"
        : "+f"(c[0]), "+f"(c[1]), "+f"(c[2]), "+f"(c[3])
        : "r"(a[0]), "r"(a[1]), "r"(a[2]), "r"(a[3]), "r"(b[0]), "r"(b[1]));
}
__device__ __forceinline__ void split2(float v, bf16& h, bf16& l) {
    h = __float2bfloat16(v);
    l = __float2bfloat16(v - __bfloat162float(h));
}

// ======================= big HMMA GEMM (qkv / out), persistent ==============
static constexpr int PITCH_G  = 80;
static constexpr int T_128    = 128 * PITCH_G;      // 10240
static constexpr int STAGE_G  = 4 * T_128;          // 40960 (Ah, Al, Bh, Bl)
static constexpr int GEMM_SMEM = 2 * STAGE_G;       // 81920

template<bool BIAS, bool SPLITOUT>
__global__ __launch_bounds__(128, 2) void hmma_gemm(
    const bf16* __restrict__ Ahi, const bf16* __restrict__ Alo,
    const bf16* __restrict__ Bhi, const bf16* __restrict__ Blo,
    const float* __restrict__ bias, float* __restrict__ C,
    bf16* __restrict__ Chi, bf16* __restrict__ Clo, int N, int K, int ntX, int ntY)
{
    extern __shared__ char smem[];
    const uint32_t sbase = smem_u32(smem);
    const int tid = threadIdx.x;
    const int wid = tid >> 5, lane = tid & 31;
    const int warpM = wid & 1, warpN = wid >> 1;
    const int NC = K >> 5;
    const int ntiles = ntX * ntY;

    for (int tile = blockIdx.x; tile < ntiles; tile += gridDim.x) {
        const int m0 = (tile / ntX) * 128;
        const int n0 = (tile % ntX) * 128;

        float acc[4][8][4];
        #pragma unroll
        for (int i = 0; i < 4; i++)
            #pragma unroll
            for (int j = 0; j < 8; j++)
                #pragma unroll
                for (int q = 0; q < 4; q++) acc[i][j][q] = 0.f;

        auto load_stage = [&](int c, int s) {
            const uint32_t sb = sbase + s * STAGE_G;
            #pragma unroll
            for (int i = 0; i < 16; i++) {
                int idx = tid + i * 128;
                int rc = idx >> 2, ch = idx & 3;
                int t = rc >> 7;
                int row = rc & 127;
                const bf16* g;
                if (t == 0)      g = Ahi + (size_t)(m0 + row) * K;
                else if (t == 1) g = Alo + (size_t)(m0 + row) * K;
                else if (t == 2) g = Bhi + (size_t)(n0 + row) * K;
                else             g = Blo + (size_t)(n0 + row) * K;
                cp16(sb + t * T_128 + row * PITCH_G + ch * 16, g + c * 32 + ch * 8);
            }
            CP_COMMIT();
        };

        load_stage(0, 0);

        for (int c = 0; c < NC; c++) {
            const int s = c & 1;
            if (c + 1 < NC) { load_stage(c + 1, s ^ 1); CP_WAIT1(); }
            else            { CP_WAIT0(); }
            __syncthreads();

            const uint32_t sb = sbase + s * STAGE_G;
            const uint32_t Ah = sb, Al = sb + T_128;
            const uint32_t Bh = sb + 2 * T_128, Bl = sb + 3 * T_128;

            #pragma unroll
            for (int ks = 0; ks < 2; ks++) {
                uint32_t ahi[4][4], alo[4][4];
                #pragma unroll
                for (int mt = 0; mt < 4; mt++) {
                    int r = warpM * 64 + mt * 16 + (lane & 15);
                    uint32_t off = r * PITCH_G + (ks * 2 + (lane >> 4)) * 16;
                    ldsm4(ahi[mt][0], ahi[mt][1], ahi[mt][2], ahi[mt][3], Ah + off);
                    ldsm4(alo[mt][0], alo[mt][1], alo[mt][2], alo[mt][3], Al + off);
                }
                #pragma unroll
                for (int tp = 0; tp < 4; tp++) {
                    uint32_t bh2[2][2], bl2[2][2];
                    int nr = warpN * 64 + tp * 16 + ((lane >> 4) << 3) + (lane & 7);
                    uint32_t off = nr * PITCH_G + (ks * 2 + ((lane >> 3) & 1)) * 16;
                    ldsm4(bh2[0][0], bh2[0][1], bh2[1][0], bh2[1][1], Bh + off);
                    ldsm4(bl2[0][0], bl2[0][1], bl2[1][0], bl2[1][1], Bl + off);
                    #pragma unroll
                    for (int mt = 0; mt < 4; mt++)
                        #pragma unroll
                        for (int p = 0; p < 2; p++) {
                            mma16816(acc[mt][2 * tp + p], ahi[mt], bh2[p]);
                            mma16816(acc[mt][2 * tp + p], ahi[mt], bl2[p]);
                            mma16816(acc[mt][2 * tp + p], alo[mt], bh2[p]);
                        }
                }
            }
            __syncthreads();
        }

        #pragma unroll
        for (int mt = 0; mt < 4; mt++) {
            int r0 = m0 + warpM * 64 + mt * 16 + (lane >> 2);
            #pragma unroll
            for (int nt = 0; nt < 8; nt++) {
                int col = n0 + warpN * 64 + nt * 8 + (lane & 3) * 2;
                if (SPLITOUT) {
                    bf16 h0, l0, h1, l1;
                    split2(acc[mt][nt][0], h0, l0);
                    split2(acc[mt][nt][1], h1, l1);
                    *(bf162*)(Chi + (size_t)r0 * N + col) = bf162(h0, h1);
                    *(bf162*)(Clo + (size_t)r0 * N + col) = bf162(l0, l1);
                    split2(acc[mt][nt][2], h0, l0);
                    split2(acc[mt][nt][3], h1, l1);
                    *(bf162*)(Chi + (size_t)(r0 + 8) * N + col) = bf162(h0, h1);
                    *(bf162*)(Clo + (size_t)(r0 + 8) * N + col) = bf162(l0, l1);
                } else {
                    float2 v0 = {acc[mt][nt][0], acc[mt][nt][1]};
                    float2 v1 = {acc[mt][nt][2], acc[mt][nt][3]};
                    if (BIAS) {
                        float2 bv = *(const float2*)(bias + col);
                        v0.x += bv.x; v0.y += bv.y;
                        v1.x += bv.x; v1.y += bv.y;
                    }
                    *(float2*)(C + (size_t)r0 * N + col)       = v0;
                    *(float2*)(C + (size_t)(r0 + 8) * N + col) = v1;
                }
            }
        }
        __syncthreads();
    }
}

// ======================= proj: elu1(slice @ projT) via HMMA =================
// 2-phase load: k[0:32] and k[32:64] as separate commit groups; first-half
// MMAs overlap second-half load.
static constexpr int PITCH_B = 144;
static constexpr int PROJ_SMEM = 4 * 18432;

__global__ __launch_bounds__(256, 2) void proj_mma()
{
    extern __shared__ char smem[];
    const uint32_t sbase = smem_u32(smem);
    const int tid = threadIdx.x;
    const int wid = tid >> 5, lane = tid & 31;
    const int warpM = wid & 3, warpN = wid >> 2;
    const int z = blockIdx.z;
    const int sel = z & 1, h = z >> 1;
    const int m0 = blockIdx.y * 128;
    const int fbase = blockIdx.x * 128;
    const int aoff = sel * 1024 + h * 64;

    // two commit groups: g=0 -> ch 0..3 (k[0:32]), g=1 -> ch 4..7 (k[32:64])
    #pragma unroll
    for (int g = 0; g < 2; g++) {
        #pragma unroll
        for (int i = 0; i < 8; i++) {
            int idx = tid + i * 256;             // 0..2047
            int t = idx >> 9;                    // 0:Ah 1:Al 2:Bh 3:Bl
            int rem = idx & 511;
            int row = rem >> 2, ch = (rem & 3) + g * 4;
            if (t < 2) {
                const bf16* gp = (t ? g_qkvl : g_qkvh) +
                    (size_t)(m0 + row) * 3072 + aoff + ch * 8;
                cp16(sbase + t * 18432 + row * PITCH_B + ch * 16, gp);
            } else {
                const bf16* gp = (t == 3 ? g_projT_lo : g_projT_hi) +
                    ((size_t)h * 256 + fbase + row) * 64 + ch * 8;
                cp16(sbase + 36864 + (t - 2) * 18432 + row * PITCH_B + ch * 16, gp);
            }
        }
        CP_COMMIT();
    }

    float acc[2][8][4];
    #pragma unroll
    for (int i = 0; i < 2; i++)
        #pragma unroll
        for (int j = 0; j < 8; j++)
            #pragma unroll
            for (int q = 0; q < 4; q++) acc[i][j][q] = 0.f;

    const uint32_t Ah = sbase, Al = sbase + 18432;
    const uint32_t Bh = sbase + 36864, Bl = sbase + 55296;

    #pragma unroll
    for (int half = 0; half < 2; half++) {
        if (half == 0) CP_WAIT1();
        else           CP_WAIT0();
        __syncthreads();
        #pragma unroll
        for (int kk = 0; kk < 2; kk++) {
            const int ks = half * 2 + kk;
            uint32_t ahi[2][4], alo[2][4];
            #pragma unroll
            for (int mt = 0; mt < 2; mt++) {
                int r = warpM * 32 + mt * 16 + (lane & 15);
                uint32_t off = r * PITCH_B + (ks * 2 + (lane >> 4)) * 16;
                ldsm4(ahi[mt][0], ahi[mt][1], ahi[mt][2], ahi[mt][3], Ah + off);
                ldsm4(alo[mt][0], alo[mt][1], alo[mt][2], alo[mt][3], Al + off);
            }
            #pragma unroll
            for (int tp = 0; tp < 4; tp++) {
                uint32_t bh[2][2], bl[2][2];
                int nr = warpN * 64 + tp * 16 + ((lane >> 4) << 3) + (lane & 7);
                uint32_t off = nr * PITCH_B + (ks * 2 + ((lane >> 3) & 1)) * 16;
                ldsm4(bh[0][0], bh[0][1], bh[1][0], bh[1][1], Bh + off);
                ldsm4(bl[0][0], bl[0][1], bl[1][0], bl[1][1], Bl + off);
                #pragma unroll
                for (int mt = 0; mt < 2; mt++)
                    #pragma unroll
                    for (int p = 0; p < 2; p++) {
                        mma16816(acc[mt][2 * tp + p], ahi[mt], bh[p]);
                        mma16816(acc[mt][2 * tp + p], ahi[mt], bl[p]);
                        mma16816(acc[mt][2 * tp + p], alo[mt], bh[p]);
                    }
            }
        }
    }

    bf16* oh = sel ? g_kph : g_qph;
    bf16* ol = sel ? g_kpl : g_qpl;
    const int b = m0 >> 12;
    const size_t bhbase = ((size_t)(b * 16 + h)) * 4096 * 256;

    float cs[16];
    #pragma unroll
    for (int i = 0; i < 16; i++) cs[i] = 0.f;

    #pragma unroll
    for (int mt = 0; mt < 2; mt++) {
        int rl0 = warpM * 32 + mt * 16 + (lane >> 2);
        #pragma unroll
        for (int nt = 0; nt < 8; nt++) {
            int col = warpN * 64 + nt * 8 + (lane & 3) * 2;
            float e[4];
            #pragma unroll
            for (int q = 0; q < 4; q++) {
                float v = acc[mt][nt][q];
                e[q] = v > 0.f ? v + 1.f : __expf(v);
                cs[nt * 2 + (q & 1)] += e[q];
            }
            int n0r = m0 + rl0 - b * 4096;
            size_t o0 = bhbase + (size_t)n0r * 256 + fbase + col;
            size_t o1 = o0 + 8 * 256;
            bf16 h0, l0, h1, l1;
            split2(e[0], h0, l0); split2(e[1], h1, l1);
            *(bf162*)(oh + o0) = bf162(h0, h1);
            *(bf162*)(ol + o0) = bf162(l0, l1);
            split2(e[2], h0, l0); split2(e[3], h1, l1);
            *(bf162*)(oh + o1) = bf162(h0, h1);
            *(bf162*)(ol + o1) = bf162(l0, l1);
        }
    }

    if (sel == 1) {
        __syncthreads();
        float* sums = (float*)smem;
        int slot = warpM * 8 + (lane >> 2);
        #pragma unroll
        for (int nt = 0; nt < 8; nt++)
            #pragma unroll
            for (int cp = 0; cp < 2; cp++) {
                int col = warpN * 64 + nt * 8 + (lane & 3) * 2 + cp;
                sums[col * 32 + slot] = cs[nt * 2 + cp];
            }
        __syncthreads();
        if (tid < 128) {
            float s = 0.f;
            #pragma unroll
            for (int i = 0; i < 32; i++) s += sums[tid * 32 + i];
            g_kspart[((size_t)blockIdx.y * 16 + h) * 256 + fbase + tid] = s;
        }
    }
}

// ======================= kv: v^T @ kproj via trans-HMMA =====================
static constexpr int KV_A_T = 32 * 144;
static constexpr int KV_B_T = 32 * 528;
static constexpr int KV_STAGE = 2 * KV_A_T + 2 * KV_B_T;
static constexpr int KV_SMEM = 2 * KV_STAGE;

__global__ __launch_bounds__(256, 2) void kv_mma()
{
    extern __shared__ char smem[];
    const uint32_t sbase = smem_u32(smem);
    const int tid = threadIdx.x;
    const int wid = tid >> 5, lane = tid & 31;
    const int warpM = wid >> 2, warpN = wid & 3;
    const int kc = blockIdx.x, bh = blockIdx.y;
    const int b = bh >> 4, h = bh & 15;

    float acc[2][8][4];
    #pragma unroll
    for (int i = 0; i < 2; i++)
        #pragma unroll
        for (int j = 0; j < 8; j++)
            #pragma unroll
            for (int q = 0; q < 4; q++) acc[i][j][q] = 0.f;

    auto load_stage = [&](int c, int s) {
        const uint32_t sb = sbase + s * KV_STAGE;
        const int n0 = kc * 1024 + c * 32;
        #pragma unroll
        for (int i = 0; i < 10; i++) {
            int idx = tid + i * 256;
            if (idx < 512) {
                int hl = idx >> 8, rem = idx & 255;
                int row = rem >> 3, ch = rem & 7;
                const bf16* g = (hl ? g_qkvl : g_qkvh) +
                    (size_t)(b * 4096 + n0 + row) * 3072 + 2048 + h * 64 + ch * 8;
                cp16(sb + hl * KV_A_T + row * 144 + ch * 16, g);
            } else {
                int idx2 = idx - 512;
                int hl = idx2 >> 10, rem = idx2 & 1023;
                int row = rem >> 5, ch = rem & 31;
                const bf16* g = (hl ? g_kpl : g_kph) +
                    ((size_t)bh * 4096 + n0 + row) * 256 + ch * 8;
                cp16(sb + 2 * KV_A_T + hl * KV_B_T + row * 528 + ch * 16, g);
            }
        }
        CP_COMMIT();
    };

    load_stage(0, 0);
    for (int c = 0; c < 32; c++) {
        const int s = c & 1;
        if (c + 1 < 32) { load_stage(c + 1, s ^ 1); CP_WAIT1(); }
        else            { CP_WAIT0(); }
        __syncthreads();

        const uint32_t sb = sbase + s * KV_STAGE;
        const uint32_t Ah = sb, Al = sb + KV_A_T;
        const uint32_t Bh = sb + 2 * KV_A_T, Bl = sb + 2 * KV_A_T + KV_B_T;

        #pragma unroll
        for (int ks = 0; ks < 2; ks++) {
            const int kbase = ks * 16;
            uint32_t ahi[2][4], alo[2][4];
            #pragma unroll
            for (int mt = 0; mt < 2; mt++) {
                int md = warpM * 32 + mt * 16 + ((lane >> 3) & 1) * 8;
                int krow = kbase + (lane >> 4) * 8 + (lane & 7);
                uint32_t off = krow * 144 + md * 2;
                ldsm4t(ahi[mt][0], ahi[mt][1], ahi[mt][2], ahi[mt][3], Ah + off);
                ldsm4t(alo[mt][0], alo[mt][1], alo[mt][2], alo[mt][3], Al + off);
            }
            #pragma unroll
            for (int tp = 0; tp < 4; tp++) {
                uint32_t bh2[2][2], bl2[2][2];
                int krow = kbase + ((lane >> 3) & 1) * 8 + (lane & 7);
                int ncol = warpN * 64 + tp * 16 + (lane >> 4) * 8;
                uint32_t off = krow * 528 + ncol * 2;
                ldsm4t(bh2[0][0], bh2[0][1], bh2[1][0], bh2[1][1], Bh + off);
                ldsm4t(bl2[0][0], bl2[0][1], bl2[1][0], bl2[1][1], Bl + off);
                #pragma unroll
                for (int mt = 0; mt < 2; mt++)
                    #pragma unroll
                    for (int p = 0; p < 2; p++) {
                        mma16816(acc[mt][2 * tp + p], ahi[mt], bh2[p]);
                        mma16816(acc[mt][2 * tp + p], ahi[mt], bl2[p]);
                        mma16816(acc[mt][2 * tp + p], alo[mt], bh2[p]);
                    }
            }
        }
        __syncthreads();
    }

    float* out = g_kvpart + ((size_t)kc * 64 + bh) * 16384;
    #pragma unroll
    for (int mt = 0; mt < 2; mt++) {
        int d0 = warpM * 32 + mt * 16 + (lane >> 2);
        #pragma unroll
        for (int nt = 0; nt < 8; nt++) {
            int col = warpN * 64 + nt * 8 + (lane & 3) * 2;
            *(float2*)(out + (size_t)d0 * 256 + col) =
                make_float2(acc[mt][nt][0], acc[mt][nt][1]);
            *(float2*)(out + (size_t)(d0 + 8) * 256 + col) =
                make_float2(acc[mt][nt][2], acc[mt][nt][3]);
        }
    }
}

// ======================= kv combine =========================================
__global__ void kv_combine()
{
    const int row = blockIdx.x;
    const int bh = blockIdx.y;
    const int f = threadIdx.x;
    float s = 0.f;
    if (row < 64) {
        #pragma unroll
        for (int kc = 0; kc < 4; kc++)
            s += g_kvpart[((size_t)kc * 64 + bh) * 16384 + row * 256 + f];
    } else if (row == 64) {
        const int b = bh >> 4, h = bh & 15;
        for (int i = 0; i < 32; i++)
            s += g_kspart[((size_t)(b * 32 + i) * 16 + h) * 256 + f];
    }
    bf16 hh, ll;
    split2(s, hh, ll);
    g_kvTh[((size_t)bh * 80 + row) * 256 + f] = hh;
    g_kvTl[((size_t)bh * 80 + row) * 256 + f] = ll;
}

// ======================= attn: qproj @ [kv|ksum] + z-norm, 3-stage ==========
static constexpr int AT_A_T = 128 * 80;
static constexpr int AT_B_T = 80 * 80;
static constexpr int AT_STAGE = 2 * AT_A_T + 2 * AT_B_T;  // 33280
static constexpr int AT_SMEM = 3 * AT_STAGE;              // 99840

__global__ __launch_bounds__(256, 2) void attn_mma()
{
    extern __shared__ char smem[];
    __shared__ float zs[128];
    const uint32_t sbase = smem_u32(smem);
    const int tid = threadIdx.x;
    const int wid = tid >> 5, lane = tid & 31;
    const int warpM = wid & 3, warpN = wid >> 2;
    const int nbase = blockIdx.x * 128;
    const int bh = blockIdx.y;
    const int b = bh >> 4, h = bh & 15;

    float acc[2][5][4];
    #pragma unroll
    for (int i = 0; i < 2; i++)
        #pragma unroll
        for (int j = 0; j < 5; j++)
            #pragma unroll
            for (int q = 0; q < 4; q++) acc[i][j][q] = 0.f;

    auto load_stage = [&](int c, int s) {
        const uint32_t sb = sbase + s * AT_STAGE;
        const int k0 = c * 32;
        #pragma unroll
        for (int i = 0; i < 7; i++) {
            int idx = tid + i * 256;
            if (idx >= 1664) break;
            if (idx < 1024) {
                int hl = idx >> 9, rem = idx & 511;
                int row = rem >> 2, ch = rem & 3;
                const bf16* g = (hl ? g_qpl : g_qph) +
                    ((size_t)bh * 4096 + nbase + row) * 256 + k0 + ch * 8;
                cp16(sb + hl * AT_A_T + row * 80 + ch * 16, g);
            } else {
                int idx2 = idx - 1024;
                int hl = idx2 >= 320 ? 1 : 0;
                int rem = idx2 - hl * 320;
                int row = rem >> 2, ch = rem & 3;
                const bf16* g = (hl ? g_kvTl : g_kvTh) +
                    ((size_t)bh * 80 + row) * 256 + k0 + ch * 8;
                cp16(sb + 2 * AT_A_T + hl * AT_B_T + row * 80 + ch * 16, g);
            }
        }
        CP_COMMIT();
    };

    load_stage(0, 0);
    load_stage(1, 1);
    for (int c = 0; c < 8; c++) {
        const int s = c - (c / 3) * 3;
        if (c + 2 < 8) {
            int s2 = (c + 2) - ((c + 2) / 3) * 3;
            load_stage(c + 2, s2);
            CP_WAIT2();
        } else if (c + 1 < 8) {
            CP_WAIT1();
        } else {
            CP_WAIT0();
        }
        __syncthreads();

        const uint32_t sb = sbase + s * AT_STAGE;
        const uint32_t Ah = sb, Al = sb + AT_A_T;
        const uint32_t Bh = sb + 2 * AT_A_T, Bl = sb + 2 * AT_A_T + AT_B_T;

        #pragma unroll
        for (int ks = 0; ks < 2; ks++) {
            uint32_t ahi[2][4], alo[2][4];
            #pragma unroll
            for (int mt = 0; mt < 2; mt++) {
                int r = warpM * 32 + mt * 16 + (lane & 15);
                uint32_t off = r * 80 + (ks * 2 + (lane >> 4)) * 16;
                ldsm4(ahi[mt][0], ahi[mt][1], ahi[mt][2], ahi[mt][3], Ah + off);
                ldsm4(alo[mt][0], alo[mt][1], alo[mt][2], alo[mt][3], Al + off);
            }
            #pragma unroll
            for (int tp = 0; tp < 2; tp++) {
                uint32_t bh2[2][2], bl2[2][2];
                int nr = warpN * 40 + tp * 16 + ((lane >> 4) << 3) + (lane & 7);
                uint32_t off = nr * 80 + (ks * 2 + ((lane >> 3) & 1)) * 16;
                ldsm4(bh2[0][0], bh2[0][1], bh2[1][0], bh2[1][1], Bh + off);
                ldsm4(bl2[0][0], bl2[0][1], bl2[1][0], bl2[1][1], Bl + off);
                #pragma unroll
                for (int mt = 0; mt < 2; mt++)
                    #pragma unroll
                    for (int p = 0; p < 2; p++) {
                        mma16816(acc[mt][2 * tp + p], ahi[mt], bh2[p]);
                        mma16816(acc[mt][2 * tp + p], ahi[mt], bl2[p]);
                        mma16816(acc[mt][2 * tp + p], alo[mt], bh2[p]);
                    }
            }
            {
                uint32_t bh2[2], bl2[2];
                int nr = warpN * 40 + 32 + (lane & 7);
                uint32_t off = nr * 80 + (ks * 2 + ((lane >> 3) & 1)) * 16;
                ldsm2(bh2[0], bh2[1], Bh + off);
                ldsm2(bl2[0], bl2[1], Bl + off);
                #pragma unroll
                for (int mt = 0; mt < 2; mt++) {
                    mma16816(acc[mt][4], ahi[mt], bh2);
                    mma16816(acc[mt][4], ahi[mt], bl2);
                    mma16816(acc[mt][4], alo[mt], bh2);
                }
            }
        }
        __syncthreads();
    }

    if (warpN == 1 && (lane & 3) == 0) {
        #pragma unroll
        for (int mt = 0; mt < 2; mt++) {
            int r0 = warpM * 32 + mt * 16 + (lane >> 2);
            zs[r0] = acc[mt][3][0];
            zs[r0 + 8] = acc[mt][3][2];
        }
    }
    __syncthreads();

    #pragma unroll
    for (int mt = 0; mt < 2; mt++) {
        int rl0 = warpM * 32 + mt * 16 + (lane >> 2);
        float zi0 = 1.0f / (zs[rl0] + 1e-8f);
        float zi1 = 1.0f / (zs[rl0 + 8] + 1e-8f);
        #pragma unroll
        for (int nt = 0; nt < 5; nt++) {
            int col = warpN * 40 + nt * 8 + (lane & 3) * 2;
            if (col >= 64) continue;
            size_t o0 = ((size_t)(b * 4096 + nbase + rl0)) * 1024 + h * 64 + col;
            size_t o1 = o0 + 8 * 1024;
            bf16 h0, l0, h1, l1;
            split2(acc[mt][nt][0] * zi0, h0, l0);
            split2(acc[mt][nt][1] * zi0, h1, l1);
            *(bf162*)(g_attn_hi + o0) = bf162(h0, h1);
            *(bf162*)(g_attn_lo + o0) = bf162(l0, l1);
            split2(acc[mt][nt][2] * zi1, h0, l0);
            split2(acc[mt][nt][3] * zi1, h1, l1);
            *(bf162*)(g_attn_hi + o1) = bf162(h0, h1);
            *(bf162*)(g_attn_lo + o1) = bf162(l0, l1);
        }
    }
}

// ======================= conversion kernels =================================
__global__ void split_f32(const float* __restrict__ in,
                          bf16* __restrict__ hi, bf16* __restrict__ lo, int n4)
{
    int i = blockIdx.x * blockDim.x + threadIdx.x;
    if (i >= n4) return;
    float4 v = ((const float4*)in)[i];
    bf16 h0, l0, h1, l1, h2, l2, h3, l3;
    split2(v.x, h0, l0); split2(v.y, h1, l1);
    split2(v.z, h2, l2); split2(v.w, h3, l3);
    ((bf162*)hi)[2 * i]     = bf162(h0, h1);
    ((bf162*)hi)[2 * i + 1] = bf162(h2, h3);
    ((bf162*)lo)[2 * i]     = bf162(l0, l1);
    ((bf162*)lo)[2 * i + 1] = bf162(l2, l3);
}

__global__ void split_wT(const float* __restrict__ w,
                         bf16* __restrict__ thi, bf16* __restrict__ tlo,
                         int K, int N)
{
    __shared__ float t[32][33];
    int bx = blockIdx.x * 32, by = blockIdx.y * 32;
    int tx = threadIdx.x, ty = threadIdx.y;
    #pragma unroll
    for (int i = 0; i < 32; i += 8)
        t[ty + i][tx] = w[(size_t)(by + ty + i) * N + bx + tx];
    __syncthreads();
    #pragma unroll
    for (int i = 0; i < 32; i += 8) {
        bf16 hh, ll;
        split2(t[tx][ty + i], hh, ll);
        size_t o = (size_t)(bx + ty + i) * K + by + tx;
        thi[o] = hh;
        tlo[o] = ll;
    }
}

__global__ void split_projT(const float* __restrict__ proj)
{
    __shared__ float t[64][33];
    const int f0 = blockIdx.x * 32;
    const int h = blockIdx.y;
    const int tid = threadIdx.x;
    #pragma unroll
    for (int i = 0; i < 8; i++) {
        int e = tid + i * 256;
        int d = e >> 5, fi = e & 31;
        t[d][fi] = proj[(size_t)h * 16384 + d * 256 + f0 + fi];
    }
    __syncthreads();
    #pragma unroll
    for (int i = 0; i < 8; i++) {
        int e = tid + i * 256;
        int fi = e >> 6, d = e & 63;
        bf16 hh, ll;
        split2(t[d][fi], hh, ll);
        size_t o = ((size_t)h * 256 + f0 + fi) * 64 + d;
        g_projT_hi[o] = hh;
        g_projT_lo[o] = ll;
    }
}

// ===========================================================================
extern "C" void kernel_launch(void* const* d_in, const int* in_sizes, int n_in,
                              void* d_out, int out_size)
{
    const float* x      = (const float*)d_in[0];
    const float* w_qkv  = (const float*)d_in[1];
    const float* proj   = (const float*)d_in[2];
    const float* w_out  = (const float*)d_in[3];
    const float* b_out  = (const float*)d_in[4];
    float* out = (float*)d_out;

    cudaFuncSetAttribute(hmma_gemm<false, true>,
                         cudaFuncAttributeMaxDynamicSharedMemorySize, GEMM_SMEM);
    cudaFuncSetAttribute(hmma_gemm<true, false>,
                         cudaFuncAttributeMaxDynamicSharedMemorySize, GEMM_SMEM);
    cudaFuncSetAttribute(proj_mma,
                         cudaFuncAttributeMaxDynamicSharedMemorySize, PROJ_SMEM);
    cudaFuncSetAttribute(kv_mma,
                         cudaFuncAttributeMaxDynamicSharedMemorySize, KV_SMEM);
    cudaFuncSetAttribute(attn_mma,
                         cudaFuncAttributeMaxDynamicSharedMemorySize, AT_SMEM);

    bf16 *xhi, *xlo, *wqh, *wql, *woh, *wol, *qh, *ql, *ahi, *alo;
    cudaGetSymbolAddress((void**)&xhi, g_xhi);
    cudaGetSymbolAddress((void**)&xlo, g_xlo);
    cudaGetSymbolAddress((void**)&wqh, g_wqkvT_hi);
    cudaGetSymbolAddress((void**)&wql, g_wqkvT_lo);
    cudaGetSymbolAddress((void**)&woh, g_woutT_hi);
    cudaGetSymbolAddress((void**)&wol, g_woutT_lo);
    cudaGetSymbolAddress((void**)&qh, g_qkvh);
    cudaGetSymbolAddress((void**)&ql, g_qkvl);
    cudaGetSymbolAddress((void**)&ahi, g_attn_hi);
    cudaGetSymbolAddress((void**)&alo, g_attn_lo);

    split_f32<<<16384, 256>>>(x, xhi, xlo, 16777216 / 4);
    split_wT<<<dim3(96, 32), dim3(32, 8)>>>(w_qkv, wqh, wql, 1024, 3072);
    split_wT<<<dim3(32, 32), dim3(32, 8)>>>(w_out, woh, wol, 1024, 1024);
    split_projT<<<dim3(8, 16), 256>>>(proj);

    hmma_gemm<false, true><<<296, 128, GEMM_SMEM>>>(
        xhi, xlo, wqh, wql, nullptr, nullptr, qh, ql, 3072, 1024, 24, 128);

    proj_mma<<<dim3(2, 128, 32), 256, PROJ_SMEM>>>();

    kv_mma<<<dim3(4, 64), 256, KV_SMEM>>>();
    kv_combine<<<dim3(80, 64), 256>>>();

    attn_mma<<<dim3(32, 64), 256, AT_SMEM>>>();

    hmma_gemm<true, false><<<296, 128, GEMM_SMEM>>>(
        ahi, alo, woh, wol, b_out, out, nullptr, nullptr, 1024, 1024, 8, 128);
}